// round 1
// baseline (speedup 1.0000x reference)
#include <cuda_runtime.h>

// Problem constants
#define BB   8
#define CC   512
#define TT   1024
#define NHH  8
#define CHH  64
#define NG   32
#define CPG  16   // channels per group

// Scratch (no cudaMalloc allowed)
__device__ float g_h[BB * CC * TT];        // 16 MB
__device__ float g_qkv[BB * 3 * CC * TT];  // 48 MB
__device__ float g_a[BB * CC * TT];        // 16 MB

// ---------------------------------------------------------------------------
// GroupNorm: one block per (batch, group). Region is contiguous 16*1024 floats.
// ---------------------------------------------------------------------------
__global__ void __launch_bounds__(256) groupnorm_kernel(
    const float* __restrict__ x, const float* __restrict__ w,
    const float* __restrict__ bvec, float* __restrict__ out)
{
    const int grp = blockIdx.x;                    // 0..255 = b*32 + g
    const float* xg = x + (size_t)grp * CPG * TT;
    float* og = out + (size_t)grp * CPG * TT;

    float s = 0.f, ss = 0.f;
    for (int i = threadIdx.x * 4; i < CPG * TT; i += 1024) {
        float4 v = *(const float4*)(xg + i);
        s  += v.x + v.y + v.z + v.w;
        ss += v.x * v.x + v.y * v.y + v.z * v.z + v.w * v.w;
    }
    __shared__ float rs[8], rss[8];
    #pragma unroll
    for (int o = 16; o > 0; o >>= 1) {
        s  += __shfl_xor_sync(0xffffffffu, s, o);
        ss += __shfl_xor_sync(0xffffffffu, ss, o);
    }
    const int warp = threadIdx.x >> 5, lane = threadIdx.x & 31;
    if (lane == 0) { rs[warp] = s; rss[warp] = ss; }
    __syncthreads();
    if (threadIdx.x == 0) {
        float a = 0.f, b = 0.f;
        #pragma unroll
        for (int i = 0; i < 8; i++) { a += rs[i]; b += rss[i]; }
        rs[0] = a; rss[0] = b;
    }
    __syncthreads();
    const float inv_n = 1.f / (float)(CPG * TT);
    const float mean = rs[0] * inv_n;
    const float var  = rss[0] * inv_n - mean * mean;
    const float rstd = rsqrtf(var + 1e-5f);
    const int cbase = (grp & (NG - 1)) * CPG;

    for (int i = threadIdx.x * 4; i < CPG * TT; i += 1024) {
        const int c = cbase + (i >> 10);           // i/TT
        const float wc = w[c] * rstd;
        const float bc = bvec[c] - mean * wc;
        float4 v = *(const float4*)(xg + i);
        float4 o;
        o.x = v.x * wc + bc; o.y = v.y * wc + bc;
        o.z = v.z * wc + bc; o.w = v.w * wc + bc;
        *(float4*)(og + i) = o;
    }
}

// ---------------------------------------------------------------------------
// SGEMM: C[b][m][n] = sum_k A[m][k] * B[b][k][n] + bias[m] (+ resid[b][m][n])
// 64x64 tile, BK=16, 256 threads, 4x4 microtile per thread.
// ---------------------------------------------------------------------------
template <bool RESID>
__global__ void __launch_bounds__(256) sgemm_kernel(
    const float* __restrict__ A, const float* __restrict__ Bm,
    const float* __restrict__ bias, const float* __restrict__ resid,
    float* __restrict__ Cm, int M, int K)
{
    __shared__ float As[16][68];   // [k][m], padded
    __shared__ float Bs[16][64];   // [k][n]

    const int n0 = blockIdx.x * 64;
    const int m0 = blockIdx.y * 64;
    const int bz = blockIdx.z;
    Bm += (size_t)bz * K * TT;
    Cm += (size_t)bz * M * TT;
    const float* rp = RESID ? resid + (size_t)bz * M * TT : nullptr;

    const int tid = threadIdx.x;
    const int tx = tid & 15, ty = tid >> 4;
    const int ar = tid >> 2, ak = (tid & 3) * 4;        // A tile: 64 rows x 16 k
    const int br = tid >> 4, bc4 = (tid & 15) * 4;      // B tile: 16 k x 64 n

    float acc[4][4] = {};

    for (int k0 = 0; k0 < K; k0 += 16) {
        const float4 av = *(const float4*)&A[(size_t)(m0 + ar) * K + k0 + ak];
        const float4 bv = *(const float4*)&Bm[(size_t)(k0 + br) * TT + n0 + bc4];
        __syncthreads();
        As[ak + 0][ar] = av.x; As[ak + 1][ar] = av.y;
        As[ak + 2][ar] = av.z; As[ak + 3][ar] = av.w;
        *(float4*)&Bs[br][bc4] = bv;
        __syncthreads();
        #pragma unroll
        for (int kk = 0; kk < 16; kk++) {
            const float4 a4 = *(const float4*)&As[kk][ty * 4];
            const float4 b4 = *(const float4*)&Bs[kk][tx * 4];
            acc[0][0] += a4.x * b4.x; acc[0][1] += a4.x * b4.y;
            acc[0][2] += a4.x * b4.z; acc[0][3] += a4.x * b4.w;
            acc[1][0] += a4.y * b4.x; acc[1][1] += a4.y * b4.y;
            acc[1][2] += a4.y * b4.z; acc[1][3] += a4.y * b4.w;
            acc[2][0] += a4.z * b4.x; acc[2][1] += a4.z * b4.y;
            acc[2][2] += a4.z * b4.z; acc[2][3] += a4.z * b4.w;
            acc[3][0] += a4.w * b4.x; acc[3][1] += a4.w * b4.y;
            acc[3][2] += a4.w * b4.z; acc[3][3] += a4.w * b4.w;
        }
    }

    #pragma unroll
    for (int i = 0; i < 4; i++) {
        const int row = m0 + ty * 4 + i;
        const float bv = bias[row];
        float4 o = make_float4(acc[i][0] + bv, acc[i][1] + bv,
                               acc[i][2] + bv, acc[i][3] + bv);
        const size_t off = (size_t)row * TT + n0 + tx * 4;
        if (RESID) {
            const float4 r = *(const float4*)&rp[off];
            o.x += r.x; o.y += r.y; o.z += r.z; o.w += r.w;
        }
        *(float4*)&Cm[off] = o;
    }
}

// ---------------------------------------------------------------------------
// Attention: flash-style. Block = (head, 64-query tile), 64 threads.
// Each thread owns one query position t; q row in regs (pre-scaled by 1/8),
// K/V 64x64 tiles in smem (broadcast float4 reads), acc column in smem.
// ---------------------------------------------------------------------------
__global__ void __launch_bounds__(64) attn_kernel(
    const float* __restrict__ qkv, float* __restrict__ a_out)
{
    __shared__ float k_sm[64][64];
    __shared__ float v_sm[64][64];
    __shared__ float acc_sm[64][64];

    const int tid = threadIdx.x;
    const int hb = blockIdx.y;            // 0..63 = b*8 + h
    const int b = hb >> 3, h = hb & 7;
    const int t = blockIdx.x * 64 + tid;

    const float* base = qkv + ((size_t)b * 3 * CC + (size_t)h * 3 * CHH) * TT;
    const float* qp = base;
    const float* kp = base + (size_t)CHH * TT;
    const float* vp = base + (size_t)2 * CHH * TT;

    float q_reg[64];
    #pragma unroll
    for (int c = 0; c < 64; c++)
        q_reg[c] = qp[(size_t)c * TT + t] * 0.125f;   // scale^2 = 1/sqrt(ch)

    #pragma unroll
    for (int c = 0; c < 64; c++) acc_sm[c][tid] = 0.f;

    float m = -1e30f, l = 0.f;

    #pragma unroll 1
    for (int sb = 0; sb < 16; sb++) {
        __syncthreads();
        // load K, V tiles (64 rows x 64 cols), float4, coalesced
        #pragma unroll
        for (int j = 0; j < 16; j++) {
            const int i = tid + 64 * j;
            const int row = i >> 4, col = (i & 15) * 4;
            const size_t goff = (size_t)row * TT + sb * 64 + col;
            *(float4*)&k_sm[row][col] = *(const float4*)&kp[goff];
            *(float4*)&v_sm[row][col] = *(const float4*)&vp[goff];
        }
        __syncthreads();

        float p[64];
        #pragma unroll
        for (int s4 = 0; s4 < 16; s4++) {
            float px = 0.f, py = 0.f, pz = 0.f, pw = 0.f;
            #pragma unroll
            for (int c = 0; c < 64; c++) {
                const float4 kv = *(const float4*)&k_sm[c][s4 * 4];
                const float q = q_reg[c];
                px += q * kv.x; py += q * kv.y;
                pz += q * kv.z; pw += q * kv.w;
            }
            p[s4 * 4 + 0] = px; p[s4 * 4 + 1] = py;
            p[s4 * 4 + 2] = pz; p[s4 * 4 + 3] = pw;
        }

        float mb = p[0];
        #pragma unroll
        for (int s = 1; s < 64; s++) mb = fmaxf(mb, p[s]);
        const float mnew = fmaxf(m, mb);
        const float alpha = __expf(m - mnew);
        float psum = 0.f;
        #pragma unroll
        for (int s = 0; s < 64; s++) {
            p[s] = __expf(p[s] - mnew);
            psum += p[s];
        }
        l = l * alpha + psum;
        m = mnew;

        #pragma unroll
        for (int c = 0; c < 64; c++) {
            float ax = 0.f, ay = 0.f, az = 0.f, aw = 0.f;
            #pragma unroll
            for (int s4 = 0; s4 < 16; s4++) {
                const float4 vv = *(const float4*)&v_sm[c][s4 * 4];
                ax += p[s4 * 4 + 0] * vv.x; ay += p[s4 * 4 + 1] * vv.y;
                az += p[s4 * 4 + 2] * vv.z; aw += p[s4 * 4 + 3] * vv.w;
            }
            acc_sm[c][tid] = acc_sm[c][tid] * alpha + (ax + ay + az + aw);
        }
    }

    const float linv = 1.f / l;
    float* ao = a_out + ((size_t)b * CC + (size_t)h * CHH) * TT + blockIdx.x * 64;
    #pragma unroll
    for (int c = 0; c < 64; c++)
        ao[(size_t)c * TT + tid] = acc_sm[c][tid] * linv;   // coalesced per c
}

// ---------------------------------------------------------------------------
extern "C" void kernel_launch(void* const* d_in, const int* in_sizes, int n_in,
                              void* d_out, int out_size)
{
    const float* x      = (const float*)d_in[0];
    const float* norm_w = (const float*)d_in[1];
    const float* norm_b = (const float*)d_in[2];
    const float* qkv_w  = (const float*)d_in[3];
    const float* qkv_b  = (const float*)d_in[4];
    const float* proj_w = (const float*)d_in[5];
    const float* proj_b = (const float*)d_in[6];
    float* out = (float*)d_out;

    float *h_buf, *qkv_buf, *a_buf;
    cudaGetSymbolAddress((void**)&h_buf, g_h);
    cudaGetSymbolAddress((void**)&qkv_buf, g_qkv);
    cudaGetSymbolAddress((void**)&a_buf, g_a);

    // 1. GroupNorm
    groupnorm_kernel<<<BB * NG, 256>>>(x, norm_w, norm_b, h_buf);
    // 2. QKV 1x1 conv: [3C, C] x [B, C, T]
    sgemm_kernel<false><<<dim3(TT / 64, 3 * CC / 64, BB), 256>>>(
        qkv_w, h_buf, qkv_b, nullptr, qkv_buf, 3 * CC, CC);
    // 3. Attention per (b, head)
    attn_kernel<<<dim3(TT / 64, BB * NHH), 64>>>(qkv_buf, a_buf);
    // 4. Proj 1x1 conv + bias + residual
    sgemm_kernel<true><<<dim3(TT / 64, CC / 64, BB), 256>>>(
        proj_w, a_buf, proj_b, x, out, CC, CC);
}

// round 4
// speedup vs baseline: 4.2075x; 4.2075x over previous
#include <cuda_runtime.h>
#include <cstdint>

#define BB   8
#define CC   512
#define TT   1024
#define NHH  8
#define CHH  64
#define NG   32
#define CPG  16

// Does this compilation pass target an arch-accel (tcgen05-capable) target?
#if (defined(__CUDA_ARCH_FEAT_SM103_ALL) || defined(__CUDA_ARCH_FEAT_SM100_ALL) || defined(__CUDA_ARCH_FEAT_SM110_ALL))
#define HAS_TCGEN05 1
#else
#define HAS_TCGEN05 0
#endif

// Scratch (no cudaMalloc allowed)
__device__ float g_h[BB * CC * TT];
__device__ float g_qkv[BB * 3 * CC * TT];
__device__ float g_a[BB * CC * TT];

// ---------------------------------------------------------------------------
// PTX helpers
// ---------------------------------------------------------------------------
__device__ __forceinline__ uint32_t smem_u32(const void* p) {
    uint32_t a;
    asm("{ .reg .u64 t; cvta.to.shared.u64 t, %1; cvt.u32.u64 %0, t; }" : "=r"(a) : "l"(p));
    return a;
}
#if HAS_TCGEN05
__device__ __forceinline__ uint32_t elect_one() {
    uint32_t pred;
    asm volatile("{\n\t.reg .pred p;\n\telect.sync _|p, 0xFFFFFFFF;\n\t"
                 "selp.b32 %0, 1, 0, p;\n\t}" : "=r"(pred));
    return pred;
}
#define TC_ALLOC(smem_addr, n) \
    asm volatile("tcgen05.alloc.cta_group::1.sync.aligned.shared::cta.b32 [%0], %1;" \
                 :: "r"((uint32_t)(smem_addr)), "r"((uint32_t)(n)) : "memory")
#define TC_DEALLOC(tmem, n) \
    asm volatile("tcgen05.dealloc.cta_group::1.sync.aligned.b32 %0, %1;" :: "r"(tmem), "r"((uint32_t)(n)))
#define TC_RELINQ() asm volatile("tcgen05.relinquish_alloc_permit.cta_group::1.sync.aligned;")
#define TC_COMMIT(mbar) \
    asm volatile("tcgen05.commit.cta_group::1.mbarrier::arrive::one.shared::cluster.b64 [%0];" \
                 :: "r"((uint32_t)(mbar)) : "memory")
#define TC_FENCE_BEFORE() asm volatile("tcgen05.fence::before_thread_sync;" ::: "memory")
#define TC_FENCE_AFTER()  asm volatile("tcgen05.fence::after_thread_sync;" ::: "memory")
#define TC_WAIT_LD() asm volatile("tcgen05.wait::ld.sync.aligned;" ::: "memory")
#define TC_WAIT_ST() asm volatile("tcgen05.wait::st.sync.aligned;" ::: "memory")
#define MBAR_INIT(mbar, cnt) \
    asm volatile("mbarrier.init.shared.b64 [%0], %1;" :: "r"((uint32_t)(mbar)), "r"((uint32_t)(cnt)) : "memory")

__device__ __forceinline__ void mbar_wait(uint32_t mbar, uint32_t parity) {
    uint32_t done;
    asm volatile("{\n\t.reg .pred p;\n\t"
                 "mbarrier.try_wait.parity.acquire.cta.shared::cta.b64 p, [%1], %2;\n\t"
                 "selp.b32 %0, 1, 0, p;\n\t}"
                 : "=r"(done) : "r"(mbar), "r"(parity) : "memory");
    if (!done) {
        asm volatile("{\n\t.reg .pred P1;\n\t"
                     "W0_%=:\n\t"
                     "mbarrier.try_wait.parity.acquire.cta.shared::cta.b64 P1, [%0], %1, 0x989680;\n\t"
                     "@P1 bra.uni W1_%=;\n\t"
                     "bra.uni W0_%=;\n\t"
                     "W1_%=:\n\t}"
                     :: "r"(mbar), "r"(parity) : "memory");
    }
}

#define TC_LD_X32(r, addr) \
    asm volatile("tcgen05.ld.sync.aligned.32x32b.x32.b32 " \
        "{%0, %1, %2, %3, %4, %5, %6, %7, %8, %9, %10, %11, %12, %13, %14, %15, " \
        " %16, %17, %18, %19, %20, %21, %22, %23, %24, %25, %26, %27, %28, %29, %30, %31}, [%32];" \
        : "=r"((r)[0]),  "=r"((r)[1]),  "=r"((r)[2]),  "=r"((r)[3]), \
          "=r"((r)[4]),  "=r"((r)[5]),  "=r"((r)[6]),  "=r"((r)[7]), \
          "=r"((r)[8]),  "=r"((r)[9]),  "=r"((r)[10]), "=r"((r)[11]), \
          "=r"((r)[12]), "=r"((r)[13]), "=r"((r)[14]), "=r"((r)[15]), \
          "=r"((r)[16]), "=r"((r)[17]), "=r"((r)[18]), "=r"((r)[19]), \
          "=r"((r)[20]), "=r"((r)[21]), "=r"((r)[22]), "=r"((r)[23]), \
          "=r"((r)[24]), "=r"((r)[25]), "=r"((r)[26]), "=r"((r)[27]), \
          "=r"((r)[28]), "=r"((r)[29]), "=r"((r)[30]), "=r"((r)[31]) \
        : "r"(addr))

#define TC_ST_X32(addr, r) \
    asm volatile("tcgen05.st.sync.aligned.32x32b.x32.b32 [%0], " \
        "{%1, %2, %3, %4, %5, %6, %7, %8, %9, %10, %11, %12, %13, %14, %15, %16, " \
        " %17, %18, %19, %20, %21, %22, %23, %24, %25, %26, %27, %28, %29, %30, %31, %32};" \
        :: "r"(addr), \
           "r"((r)[0]),  "r"((r)[1]),  "r"((r)[2]),  "r"((r)[3]), \
           "r"((r)[4]),  "r"((r)[5]),  "r"((r)[6]),  "r"((r)[7]), \
           "r"((r)[8]),  "r"((r)[9]),  "r"((r)[10]), "r"((r)[11]), \
           "r"((r)[12]), "r"((r)[13]), "r"((r)[14]), "r"((r)[15]), \
           "r"((r)[16]), "r"((r)[17]), "r"((r)[18]), "r"((r)[19]), \
           "r"((r)[20]), "r"((r)[21]), "r"((r)[22]), "r"((r)[23]), \
           "r"((r)[24]), "r"((r)[25]), "r"((r)[26]), "r"((r)[27]), \
           "r"((r)[28]), "r"((r)[29]), "r"((r)[30]), "r"((r)[31]) \
        : "memory")

__device__ __forceinline__ void mma_tf32_ss(uint32_t d, uint64_t ad, uint64_t bd,
                                            uint32_t idesc, bool acc) {
    uint32_t en = acc ? 1u : 0u;
    asm volatile("{\n\t.reg .pred p;\n\tsetp.ne.u32 p, %5, 0;\n\t"
                 "tcgen05.mma.cta_group::1.kind::tf32 [%0], %1, %2, %3, {%4, %4, %4, %4}, p;\n\t}"
                 :: "r"(d), "l"(ad), "l"(bd), "r"(idesc), "r"(0u), "r"(en) : "memory");
}
__device__ __forceinline__ void mma_tf32_ts(uint32_t d, uint32_t a, uint64_t bd,
                                            uint32_t idesc, bool acc) {
    uint32_t en = acc ? 1u : 0u;
    asm volatile("{\n\t.reg .pred p;\n\tsetp.ne.u32 p, %5, 0;\n\t"
                 "tcgen05.mma.cta_group::1.kind::tf32 [%0], [%1], %2, %3, {%4, %4, %4, %4}, p;\n\t}"
                 :: "r"(d), "r"(a), "l"(bd), "r"(idesc), "r"(0u), "r"(en) : "memory");
}

__device__ __forceinline__ uint64_t make_desc(uint32_t addr) {
    const uint64_t base = (uint64_t(2) << 61) | (uint64_t(1) << 46)
                        | (uint64_t(64) << 32) | (uint64_t(1) << 16);
    return base | ((uint64_t)(addr >> 4) & 0x3FFF);
}
// Blocked-atom SW128 byte offset: atom = 8 rows x 32 floats (128B rows).
// FIX (R4): within-atom k must be masked to the 32-float atom width.
__device__ __forceinline__ uint32_t toff(int r, int k, int R) {
    uint32_t b = ((uint32_t)((r >> 3) + (k >> 5) * R) << 10) + ((r & 7) << 7)
               + ((uint32_t)(k & 31) << 2);
    return b ^ ((b >> 3) & 0x70);
}
#define IDESC(M, N) ((1u << 4) | (2u << 7) | (2u << 10) | ((uint32_t)((N) / 8) << 17) | ((uint32_t)((M) / 16) << 24))
#endif  // HAS_TCGEN05

// ---------------------------------------------------------------------------
// GroupNorm (arch-independent)
// ---------------------------------------------------------------------------
__global__ void __launch_bounds__(256) groupnorm_kernel(
    const float* __restrict__ x, const float* __restrict__ w,
    const float* __restrict__ bvec, float* __restrict__ out)
{
    const int grp = blockIdx.x;
    const float* xg = x + (size_t)grp * CPG * TT;
    float* og = out + (size_t)grp * CPG * TT;

    float s = 0.f, ss = 0.f;
    for (int i = threadIdx.x * 4; i < CPG * TT; i += 1024) {
        float4 v = *(const float4*)(xg + i);
        s  += v.x + v.y + v.z + v.w;
        ss += v.x * v.x + v.y * v.y + v.z * v.z + v.w * v.w;
    }
    __shared__ float rs[8], rss[8];
    #pragma unroll
    for (int o = 16; o > 0; o >>= 1) {
        s  += __shfl_xor_sync(0xffffffffu, s, o);
        ss += __shfl_xor_sync(0xffffffffu, ss, o);
    }
    const int warp = threadIdx.x >> 5, lane = threadIdx.x & 31;
    if (lane == 0) { rs[warp] = s; rss[warp] = ss; }
    __syncthreads();
    if (threadIdx.x == 0) {
        float a = 0.f, b = 0.f;
        #pragma unroll
        for (int i = 0; i < 8; i++) { a += rs[i]; b += rss[i]; }
        rs[0] = a; rss[0] = b;
    }
    __syncthreads();
    const float inv_n = 1.f / (float)(CPG * TT);
    const float mean = rs[0] * inv_n;
    const float var  = rss[0] * inv_n - mean * mean;
    const float rstd = rsqrtf(var + 1e-5f);
    const int cbase = (grp & (NG - 1)) * CPG;

    for (int i = threadIdx.x * 4; i < CPG * TT; i += 1024) {
        const int c = cbase + (i >> 10);
        const float wc = w[c] * rstd;
        const float bc = bvec[c] - mean * wc;
        float4 v = *(const float4*)(xg + i);
        float4 o;
        o.x = v.x * wc + bc; o.y = v.y * wc + bc;
        o.z = v.z * wc + bc; o.w = v.w * wc + bc;
        *(float4*)(og + i) = o;
    }
}

// ===========================================================================
// tcgen05 tf32 pipeline (no-op on non-accel cubins)
// ===========================================================================
template <bool RESID>
__global__ void __launch_bounds__(128) gemm_tc(
    const float* __restrict__ A, const float* __restrict__ Bm,
    const float* __restrict__ bias, const float* __restrict__ resid,
    float* __restrict__ C, int M, int K)
{
#if HAS_TCGEN05
    extern __shared__ char dsm_raw[];
    const uint32_t sraw = smem_u32(dsm_raw);
    const uint32_t sal = (sraw + 1023) & ~1023u;
    char* smb = dsm_raw + (sal - sraw);
    char* Ab[2] = { smb, smb + 32768 };
    char* Bb[2] = { smb + 16384, smb + 49152 };
    const uint32_t Aaddr[2] = { sal, sal + 32768 };
    const uint32_t Baddr[2] = { sal + 16384, sal + 49152 };

    __shared__ uint32_t s_tmem;
    __shared__ __align__(8) uint64_t s_mbar[2];

    const int tid = threadIdx.x;
    const int wid = tid >> 5;
    const int n0 = blockIdx.x * 128;
    const int m0 = blockIdx.y * 128;
    const int bz = blockIdx.z;
    Bm += (size_t)bz * K * TT;
    C  += (size_t)bz * M * TT;
    const float* rp = RESID ? resid + (size_t)bz * M * TT : nullptr;

    if (wid == 0) TC_ALLOC(smem_u32(&s_tmem), 128);
    if (tid == 0) { MBAR_INIT(smem_u32(&s_mbar[0]), 1); MBAR_INIT(smem_u32(&s_mbar[1]), 1); }
    __syncthreads();
    uint32_t tmem;
    asm volatile("ld.shared.b32 %0, [%1];" : "=r"(tmem) : "r"(smem_u32(&s_tmem)));
    const uint32_t mb0 = smem_u32(&s_mbar[0]), mb1 = smem_u32(&s_mbar[1]);
    const uint32_t idesc = IDESC(128, 128);

    const int nk = K / 32;
    int use0 = 0, use1 = 0;

    for (int i = 0; i < nk; i++) {
        const int bsel = i & 1;
        const int ub = bsel ? use1 : use0;
        if (ub > 0) mbar_wait(bsel ? mb1 : mb0, (uint32_t)((ub - 1) & 1));

        {   // stage A [128m x 32k] K-major
            const float* Ak = A + (size_t)m0 * K + i * 32;
            #pragma unroll
            for (int p = 0; p < 4; p++) {
                const int row = (tid >> 2) + p * 32;
                const int kk = (tid & 3) * 8;
                const float4 v0 = *(const float4*)&Ak[(size_t)row * K + kk];
                const float4 v1 = *(const float4*)&Ak[(size_t)row * K + kk + 4];
                *(float4*)(Ab[bsel] + toff(row, kk, 16)) = v0;
                *(float4*)(Ab[bsel] + toff(row, kk + 4, 16)) = v1;
            }
        }
        {   // stage B [128n x 32k] K-major via transpose of h[k][n]
            const float* Bk = Bm + (size_t)(i * 32) * TT + n0;
            #pragma unroll
            for (int p = 0; p < 8; p++) {
                const int krow = tid >> 2;
                const int nn = (tid & 3) * 4 + p * 16;
                const float4 v = *(const float4*)&Bk[(size_t)krow * TT + nn];
                char* bb = Bb[bsel];
                *(float*)(bb + toff(nn + 0, krow, 16)) = v.x;
                *(float*)(bb + toff(nn + 1, krow, 16)) = v.y;
                *(float*)(bb + toff(nn + 2, krow, 16)) = v.z;
                *(float*)(bb + toff(nn + 3, krow, 16)) = v.w;
            }
        }
        __syncthreads();
        if (wid == 0 && elect_one()) {
            const uint64_t ad = make_desc(Aaddr[bsel]);
            const uint64_t bd = make_desc(Baddr[bsel]);
            #pragma unroll
            for (int j = 0; j < 4; j++)
                mma_tf32_ss(tmem, ad + j * 2, bd + j * 2, idesc, (i > 0) || (j > 0));
            TC_COMMIT(bsel ? mb1 : mb0);
        }
        if (bsel) use1++; else use0++;
        __syncthreads();
    }
    {
        const int lb = (nk - 1) & 1;
        const int ub = lb ? use1 : use0;
        mbar_wait(lb ? mb1 : mb0, (uint32_t)((ub - 1) & 1));
    }
    TC_FENCE_AFTER();
    __syncthreads();

    float* tsm = (float*)smb;   // [32][133]
    const int lane = tid & 31;
    for (int c4 = 0; c4 < 4; c4++) {
        uint32_t regs[32];
        TC_LD_X32(regs, tmem + c4 * 32);
        TC_WAIT_LD();
        __syncthreads();
        const int myrow = wid * 32 + lane;
        #pragma unroll
        for (int j = 0; j < 32; j++) tsm[j * 133 + myrow] = __uint_as_float(regs[j]);
        __syncthreads();
        const int n = tid & 31;
        #pragma unroll
        for (int q = 0; q < 32; q++) {
            const int m = (tid >> 5) + q * 4;
            float v = tsm[n * 133 + m] + bias[m0 + m];
            const size_t off = (size_t)(m0 + m) * TT + n0 + c4 * 32 + n;
            if (RESID) v += rp[off];
            C[off] = v;
        }
        __syncthreads();
    }
    if (wid == 0) { TC_RELINQ(); TC_DEALLOC(tmem, 128); }
#endif
}

__global__ void __launch_bounds__(128) attn_tc(
    const float* __restrict__ qkv, float* __restrict__ a_out)
{
#if HAS_TCGEN05
    extern __shared__ char dsm_raw[];
    const uint32_t sraw = smem_u32(dsm_raw);
    const uint32_t sal = (sraw + 1023) & ~1023u;
    char* smb = dsm_raw + (sal - sraw);
    char* Qb = smb;
    char* Kb = smb + 32768;
    char* Vb = smb + 65536;
    const uint32_t Qaddr = sal, Kaddr = sal + 32768, Vaddr = sal + 65536;

    __shared__ uint32_t s_tmem;
    __shared__ __align__(8) uint64_t s_mbar;

    const int tid = threadIdx.x;
    const int wid = tid >> 5;
    const int bh = blockIdx.y;
    const int b = bh >> 3, h = bh & 7;
    const int t0 = blockIdx.x * 128;

    const float* qp = qkv + ((size_t)(b * 3 * CC) + (size_t)h * 3 * CHH) * TT;
    const float* kp = qp + (size_t)CHH * TT;
    const float* vp = qp + (size_t)2 * CHH * TT;

    if (wid == 0) TC_ALLOC(smem_u32(&s_tmem), 256);
    if (tid == 0) MBAR_INIT(smem_u32(&s_mbar), 1);
    __syncthreads();
    uint32_t tmem;
    asm volatile("ld.shared.b32 %0, [%1];" : "=r"(tmem) : "r"(smem_u32(&s_tmem)));
    const uint32_t mb = smem_u32(&s_mbar);
    const uint32_t tS = tmem;
    const uint32_t tO = tmem + 128;
    const uint32_t idS = IDESC(128, 128);
    const uint32_t idO = IDESC(128, 64);
    uint32_t ph = 0;

    {   // stage Q once (transposed, pre-scaled)
        const int c = tid >> 1;
        #pragma unroll
        for (int p = 0; p < 16; p++) {
            const int t = (tid & 1) * 4 + p * 8;
            const float4 v = *(const float4*)&qp[(size_t)c * TT + t0 + t];
            *(float*)(Qb + toff(t + 0, c, 16)) = v.x * 0.125f;
            *(float*)(Qb + toff(t + 1, c, 16)) = v.y * 0.125f;
            *(float*)(Qb + toff(t + 2, c, 16)) = v.z * 0.125f;
            *(float*)(Qb + toff(t + 3, c, 16)) = v.w * 0.125f;
        }
    }

    const uint64_t qdesc = make_desc(Qaddr);
    const uint64_t kdesc = make_desc(Kaddr);
    const uint64_t vdesc = make_desc(Vaddr);
    const uint32_t woff = (uint32_t)wid << 21;

    float mrow = -1e30f;

    // Pass A: row max
    for (int st = 0; st < 8; st++) {
        const int s0 = st * 128;
        {
            const int c = tid >> 1;
            #pragma unroll
            for (int p = 0; p < 16; p++) {
                const int s = (tid & 1) * 4 + p * 8;
                const float4 v = *(const float4*)&kp[(size_t)c * TT + s0 + s];
                *(float*)(Kb + toff(s + 0, c, 16)) = v.x;
                *(float*)(Kb + toff(s + 1, c, 16)) = v.y;
                *(float*)(Kb + toff(s + 2, c, 16)) = v.z;
                *(float*)(Kb + toff(s + 3, c, 16)) = v.w;
            }
        }
        __syncthreads();
        if (wid == 0 && elect_one()) {
            #pragma unroll
            for (int j = 0; j < 8; j++) {
                const uint64_t off = (uint64_t)((j & 3) * 2 + (j >> 2) * 1024);
                mma_tf32_ss(tS, qdesc + off, kdesc + off, idS, j > 0);
            }
            TC_COMMIT(mb);
        }
        mbar_wait(mb, ph); ph ^= 1;
        TC_FENCE_AFTER();
        for (int c4 = 0; c4 < 4; c4++) {
            uint32_t r[32];
            TC_LD_X32(r, tS + c4 * 32);
            TC_WAIT_LD();
            #pragma unroll
            for (int j = 0; j < 32; j++) mrow = fmaxf(mrow, __uint_as_float(r[j]));
        }
        __syncthreads();
    }

    // Pass B: P = exp(S-m), O += P V^T
    float l = 0.f;
    for (int st = 0; st < 8; st++) {
        const int s0 = st * 128;
        {
            const int c = tid >> 1;
            #pragma unroll
            for (int p = 0; p < 16; p++) {
                const int s = (tid & 1) * 4 + p * 8;
                const float4 v = *(const float4*)&kp[(size_t)c * TT + s0 + s];
                *(float*)(Kb + toff(s + 0, c, 16)) = v.x;
                *(float*)(Kb + toff(s + 1, c, 16)) = v.y;
                *(float*)(Kb + toff(s + 2, c, 16)) = v.z;
                *(float*)(Kb + toff(s + 3, c, 16)) = v.w;
                const float4 w = *(const float4*)&vp[(size_t)c * TT + s0 + s];
                *(float4*)(Vb + toff(c, s, 8)) = w;
            }
        }
        __syncthreads();
        if (wid == 0 && elect_one()) {
            #pragma unroll
            for (int j = 0; j < 8; j++) {
                const uint64_t off = (uint64_t)((j & 3) * 2 + (j >> 2) * 1024);
                mma_tf32_ss(tS, qdesc + off, kdesc + off, idS, j > 0);
            }
            TC_COMMIT(mb);
        }
        mbar_wait(mb, ph); ph ^= 1;
        TC_FENCE_AFTER();
        for (int c4 = 0; c4 < 4; c4++) {
            uint32_t r[32];
            TC_LD_X32(r, tS + c4 * 32);
            TC_WAIT_LD();
            #pragma unroll
            for (int j = 0; j < 32; j++) {
                const float pv = __expf(__uint_as_float(r[j]) - mrow);
                l += pv;
                r[j] = __float_as_uint(pv);
            }
            TC_ST_X32(tS + c4 * 32 + woff, r);
        }
        TC_WAIT_ST();
        TC_FENCE_BEFORE();
        __syncthreads();
        if (wid == 0 && elect_one()) {
            TC_FENCE_AFTER();
            #pragma unroll
            for (int j = 0; j < 16; j++) {
                const uint64_t off = (uint64_t)((j & 3) * 2 + (j >> 2) * 512);
                mma_tf32_ts(tO, tS + j * 8, vdesc + off, idO, (st > 0) || (j > 0));
            }
            TC_COMMIT(mb);
        }
        mbar_wait(mb, ph); ph ^= 1;
        __syncthreads();
    }

    // epilogue
    TC_FENCE_AFTER();
    uint32_t o0[32], o1[32];
    TC_LD_X32(o0, tO);
    TC_LD_X32(o1, tO + 32);
    TC_WAIT_LD();
    const float inv = 1.f / l;
    float* tsm2 = (float*)smb;   // [64][129]
    __syncthreads();
    #pragma unroll
    for (int c = 0; c < 32; c++) tsm2[c * 129 + tid] = __uint_as_float(o0[c]) * inv;
    #pragma unroll
    for (int c = 0; c < 32; c++) tsm2[(c + 32) * 129 + tid] = __uint_as_float(o1[c]) * inv;
    __syncthreads();
    float* ao = a_out + ((size_t)(b * CC) + (size_t)h * CHH) * TT + t0;
    for (int q = 0; q < 64; q++)
        ao[(size_t)q * TT + tid] = tsm2[q * 129 + tid];

    __syncthreads();
    if (wid == 0) { TC_RELINQ(); TC_DEALLOC(tmem, 256); }
#endif
}

// ===========================================================================
// fp32 fallback pipeline (R1, proven) — no-op on accel cubins
// ===========================================================================
template <bool RESID>
__global__ void __launch_bounds__(256) sgemm_fp(
    const float* __restrict__ A, const float* __restrict__ Bm,
    const float* __restrict__ bias, const float* __restrict__ resid,
    float* __restrict__ Cm, int M, int K)
{
#if !HAS_TCGEN05
    __shared__ float As[16][68];
    __shared__ float Bs[16][64];

    const int n0 = blockIdx.x * 64;
    const int m0 = blockIdx.y * 64;
    const int bz = blockIdx.z;
    Bm += (size_t)bz * K * TT;
    Cm += (size_t)bz * M * TT;
    const float* rp = RESID ? resid + (size_t)bz * M * TT : nullptr;

    const int tid = threadIdx.x;
    const int tx = tid & 15, ty = tid >> 4;
    const int ar = tid >> 2, ak = (tid & 3) * 4;
    const int br = tid >> 4, bc4 = (tid & 15) * 4;

    float acc[4][4] = {};

    for (int k0 = 0; k0 < K; k0 += 16) {
        const float4 av = *(const float4*)&A[(size_t)(m0 + ar) * K + k0 + ak];
        const float4 bv = *(const float4*)&Bm[(size_t)(k0 + br) * TT + n0 + bc4];
        __syncthreads();
        As[ak + 0][ar] = av.x; As[ak + 1][ar] = av.y;
        As[ak + 2][ar] = av.z; As[ak + 3][ar] = av.w;
        *(float4*)&Bs[br][bc4] = bv;
        __syncthreads();
        #pragma unroll
        for (int kk = 0; kk < 16; kk++) {
            const float4 a4 = *(const float4*)&As[kk][ty * 4];
            const float4 b4 = *(const float4*)&Bs[kk][tx * 4];
            acc[0][0] += a4.x * b4.x; acc[0][1] += a4.x * b4.y;
            acc[0][2] += a4.x * b4.z; acc[0][3] += a4.x * b4.w;
            acc[1][0] += a4.y * b4.x; acc[1][1] += a4.y * b4.y;
            acc[1][2] += a4.y * b4.z; acc[1][3] += a4.y * b4.w;
            acc[2][0] += a4.z * b4.x; acc[2][1] += a4.z * b4.y;
            acc[2][2] += a4.z * b4.z; acc[2][3] += a4.z * b4.w;
            acc[3][0] += a4.w * b4.x; acc[3][1] += a4.w * b4.y;
            acc[3][2] += a4.w * b4.z; acc[3][3] += a4.w * b4.w;
        }
    }

    #pragma unroll
    for (int i = 0; i < 4; i++) {
        const int row = m0 + ty * 4 + i;
        const float bv = bias[row];
        float4 o = make_float4(acc[i][0] + bv, acc[i][1] + bv,
                               acc[i][2] + bv, acc[i][3] + bv);
        const size_t off = (size_t)row * TT + n0 + tx * 4;
        if (RESID) {
            const float4 r = *(const float4*)&rp[off];
            o.x += r.x; o.y += r.y; o.z += r.z; o.w += r.w;
        }
        *(float4*)&Cm[off] = o;
    }
#endif
}

__global__ void __launch_bounds__(64) attn_fp(
    const float* __restrict__ qkv, float* __restrict__ a_out)
{
#if !HAS_TCGEN05
    __shared__ float k_sm[64][64];
    __shared__ float v_sm[64][64];
    __shared__ float acc_sm[64][64];

    const int tid = threadIdx.x;
    const int hb = blockIdx.y;
    const int b = hb >> 3, h = hb & 7;
    const int t = blockIdx.x * 64 + tid;

    const float* base = qkv + ((size_t)b * 3 * CC + (size_t)h * 3 * CHH) * TT;
    const float* qp = base;
    const float* kp = base + (size_t)CHH * TT;
    const float* vp = base + (size_t)2 * CHH * TT;

    float q_reg[64];
    #pragma unroll
    for (int c = 0; c < 64; c++)
        q_reg[c] = qp[(size_t)c * TT + t] * 0.125f;

    #pragma unroll
    for (int c = 0; c < 64; c++) acc_sm[c][tid] = 0.f;

    float m = -1e30f, l = 0.f;

    #pragma unroll 1
    for (int sb = 0; sb < 16; sb++) {
        __syncthreads();
        #pragma unroll
        for (int j = 0; j < 16; j++) {
            const int i = tid + 64 * j;
            const int row = i >> 4, col = (i & 15) * 4;
            const size_t goff = (size_t)row * TT + sb * 64 + col;
            *(float4*)&k_sm[row][col] = *(const float4*)&kp[goff];
            *(float4*)&v_sm[row][col] = *(const float4*)&vp[goff];
        }
        __syncthreads();

        float p[64];
        #pragma unroll
        for (int s4 = 0; s4 < 16; s4++) {
            float px = 0.f, py = 0.f, pz = 0.f, pw = 0.f;
            #pragma unroll
            for (int c = 0; c < 64; c++) {
                const float4 kv = *(const float4*)&k_sm[c][s4 * 4];
                const float q = q_reg[c];
                px += q * kv.x; py += q * kv.y;
                pz += q * kv.z; pw += q * kv.w;
            }
            p[s4 * 4 + 0] = px; p[s4 * 4 + 1] = py;
            p[s4 * 4 + 2] = pz; p[s4 * 4 + 3] = pw;
        }

        float mb = p[0];
        #pragma unroll
        for (int s = 1; s < 64; s++) mb = fmaxf(mb, p[s]);
        const float mnew = fmaxf(m, mb);
        const float alpha = __expf(m - mnew);
        float psum = 0.f;
        #pragma unroll
        for (int s = 0; s < 64; s++) {
            p[s] = __expf(p[s] - mnew);
            psum += p[s];
        }
        l = l * alpha + psum;
        m = mnew;

        #pragma unroll
        for (int c = 0; c < 64; c++) {
            float ax = 0.f, ay = 0.f, az = 0.f, aw = 0.f;
            #pragma unroll
            for (int s4 = 0; s4 < 16; s4++) {
                const float4 vv = *(const float4*)&v_sm[c][s4 * 4];
                ax += p[s4 * 4 + 0] * vv.x; ay += p[s4 * 4 + 1] * vv.y;
                az += p[s4 * 4 + 2] * vv.z; aw += p[s4 * 4 + 3] * vv.w;
            }
            acc_sm[c][tid] = acc_sm[c][tid] * alpha + (ax + ay + az + aw);
        }
    }

    const float linv = 1.f / l;
    float* ao = a_out + ((size_t)b * CC + (size_t)h * CHH) * TT + blockIdx.x * 64;
    #pragma unroll
    for (int c = 0; c < 64; c++)
        ao[(size_t)c * TT + tid] = acc_sm[c][tid] * linv;
#endif
}

// ---------------------------------------------------------------------------
extern "C" void kernel_launch(void* const* d_in, const int* in_sizes, int n_in,
                              void* d_out, int out_size)
{
    const float* x      = (const float*)d_in[0];
    const float* norm_w = (const float*)d_in[1];
    const float* norm_b = (const float*)d_in[2];
    const float* qkv_w  = (const float*)d_in[3];
    const float* qkv_b  = (const float*)d_in[4];
    const float* proj_w = (const float*)d_in[5];
    const float* proj_b = (const float*)d_in[6];
    float* out = (float*)d_out;

    float *h_buf, *qkv_buf, *a_buf;
    cudaGetSymbolAddress((void**)&h_buf, g_h);
    cudaGetSymbolAddress((void**)&qkv_buf, g_qkv);
    cudaGetSymbolAddress((void**)&a_buf, g_a);

    const int GEMM_SMEM = 66560;
    const int ATTN_SMEM = 99328;
    cudaFuncSetAttribute(gemm_tc<false>, cudaFuncAttributeMaxDynamicSharedMemorySize, GEMM_SMEM);
    cudaFuncSetAttribute(gemm_tc<true>,  cudaFuncAttributeMaxDynamicSharedMemorySize, GEMM_SMEM);
    cudaFuncSetAttribute(attn_tc, cudaFuncAttributeMaxDynamicSharedMemorySize, ATTN_SMEM);

    // 1. GroupNorm (shared by both paths)
    groupnorm_kernel<<<BB * NG, 256>>>(x, norm_w, norm_b, h_buf);

    // 2. QKV (one path does work per cubin)
    gemm_tc<false><<<dim3(TT / 128, 3 * CC / 128, BB), 128, GEMM_SMEM>>>(
        qkv_w, h_buf, qkv_b, nullptr, qkv_buf, 3 * CC, CC);
    sgemm_fp<false><<<dim3(TT / 64, 3 * CC / 64, BB), 256>>>(
        qkv_w, h_buf, qkv_b, nullptr, qkv_buf, 3 * CC, CC);

    // 3. Attention
    attn_tc<<<dim3(TT / 128, BB * NHH), 128, ATTN_SMEM>>>(qkv_buf, a_buf);
    attn_fp<<<dim3(TT / 64, BB * NHH), 64>>>(qkv_buf, a_buf);

    // 4. Proj + bias + residual
    gemm_tc<true><<<dim3(TT / 128, CC / 128, BB), 128, GEMM_SMEM>>>(
        proj_w, a_buf, proj_b, x, out, CC, CC);
    sgemm_fp<true><<<dim3(TT / 64, CC / 64, BB), 256>>>(
        proj_w, a_buf, proj_b, x, out, CC, CC);
}

// round 7
// speedup vs baseline: 5.7493x; 1.3664x over previous
#include <cuda_runtime.h>
#include <cstdint>

#define BB   8
#define CC   512
#define TT   1024
#define NHH  8
#define CHH  64
#define NG   32
#define CPG  16

#if (defined(__CUDA_ARCH_FEAT_SM103_ALL) || defined(__CUDA_ARCH_FEAT_SM100_ALL) || defined(__CUDA_ARCH_FEAT_SM110_ALL))
#define HAS_TCGEN05 1
#else
#define HAS_TCGEN05 0
#endif

__device__ float g_h[BB * CC * TT];
__device__ float g_qkv[BB * 3 * CC * TT];
__device__ float g_a[BB * CC * TT];

__device__ __forceinline__ uint32_t smem_u32(const void* p) {
    uint32_t a;
    asm("{ .reg .u64 t; cvta.to.shared.u64 t, %1; cvt.u32.u64 %0, t; }" : "=r"(a) : "l"(p));
    return a;
}
#if HAS_TCGEN05
__device__ __forceinline__ uint32_t elect_one() {
    uint32_t pred;
    asm volatile("{\n\t.reg .pred p;\n\telect.sync _|p, 0xFFFFFFFF;\n\t"
                 "selp.b32 %0, 1, 0, p;\n\t}" : "=r"(pred));
    return pred;
}
#define TC_ALLOC(smem_addr, n) \
    asm volatile("tcgen05.alloc.cta_group::1.sync.aligned.shared::cta.b32 [%0], %1;" \
                 :: "r"((uint32_t)(smem_addr)), "r"((uint32_t)(n)) : "memory")
#define TC_DEALLOC(tmem, n) \
    asm volatile("tcgen05.dealloc.cta_group::1.sync.aligned.b32 %0, %1;" :: "r"(tmem), "r"((uint32_t)(n)))
#define TC_RELINQ() asm volatile("tcgen05.relinquish_alloc_permit.cta_group::1.sync.aligned;")
#define TC_COMMIT(mbar) \
    asm volatile("tcgen05.commit.cta_group::1.mbarrier::arrive::one.shared::cluster.b64 [%0];" \
                 :: "r"((uint32_t)(mbar)) : "memory")
#define TC_FENCE_BEFORE() asm volatile("tcgen05.fence::before_thread_sync;" ::: "memory")
#define TC_FENCE_AFTER()  asm volatile("tcgen05.fence::after_thread_sync;" ::: "memory")
#define TC_WAIT_LD() asm volatile("tcgen05.wait::ld.sync.aligned;" ::: "memory")
#define TC_WAIT_ST() asm volatile("tcgen05.wait::st.sync.aligned;" ::: "memory")
#define MBAR_INIT(mbar, cnt) \
    asm volatile("mbarrier.init.shared.b64 [%0], %1;" :: "r"((uint32_t)(mbar)), "r"((uint32_t)(cnt)) : "memory")

__device__ __forceinline__ void mbar_wait(uint32_t mbar, uint32_t parity) {
    uint32_t done;
    asm volatile("{\n\t.reg .pred p;\n\t"
                 "mbarrier.try_wait.parity.acquire.cta.shared::cta.b64 p, [%1], %2;\n\t"
                 "selp.b32 %0, 1, 0, p;\n\t}"
                 : "=r"(done) : "r"(mbar), "r"(parity) : "memory");
    if (!done) {
        asm volatile("{\n\t.reg .pred P1;\n\t"
                     "W0_%=:\n\t"
                     "mbarrier.try_wait.parity.acquire.cta.shared::cta.b64 P1, [%0], %1, 0x989680;\n\t"
                     "@P1 bra.uni W1_%=;\n\t"
                     "bra.uni W0_%=;\n\t"
                     "W1_%=:\n\t}"
                     :: "r"(mbar), "r"(parity) : "memory");
    }
}

#define TC_LD_X32(r, addr) \
    asm volatile("tcgen05.ld.sync.aligned.32x32b.x32.b32 " \
        "{%0, %1, %2, %3, %4, %5, %6, %7, %8, %9, %10, %11, %12, %13, %14, %15, " \
        " %16, %17, %18, %19, %20, %21, %22, %23, %24, %25, %26, %27, %28, %29, %30, %31}, [%32];" \
        : "=r"((r)[0]),  "=r"((r)[1]),  "=r"((r)[2]),  "=r"((r)[3]), \
          "=r"((r)[4]),  "=r"((r)[5]),  "=r"((r)[6]),  "=r"((r)[7]), \
          "=r"((r)[8]),  "=r"((r)[9]),  "=r"((r)[10]), "=r"((r)[11]), \
          "=r"((r)[12]), "=r"((r)[13]), "=r"((r)[14]), "=r"((r)[15]), \
          "=r"((r)[16]), "=r"((r)[17]), "=r"((r)[18]), "=r"((r)[19]), \
          "=r"((r)[20]), "=r"((r)[21]), "=r"((r)[22]), "=r"((r)[23]), \
          "=r"((r)[24]), "=r"((r)[25]), "=r"((r)[26]), "=r"((r)[27]), \
          "=r"((r)[28]), "=r"((r)[29]), "=r"((r)[30]), "=r"((r)[31]) \
        : "r"(addr))

#define TC_ST_X32(addr, r) \
    asm volatile("tcgen05.st.sync.aligned.32x32b.x32.b32 [%0], " \
        "{%1, %2, %3, %4, %5, %6, %7, %8, %9, %10, %11, %12, %13, %14, %15, %16, " \
        " %17, %18, %19, %20, %21, %22, %23, %24, %25, %26, %27, %28, %29, %30, %31, %32};" \
        :: "r"(addr), \
           "r"((r)[0]),  "r"((r)[1]),  "r"((r)[2]),  "r"((r)[3]), \
           "r"((r)[4]),  "r"((r)[5]),  "r"((r)[6]),  "r"((r)[7]), \
           "r"((r)[8]),  "r"((r)[9]),  "r"((r)[10]), "r"((r)[11]), \
           "r"((r)[12]), "r"((r)[13]), "r"((r)[14]), "r"((r)[15]), \
           "r"((r)[16]), "r"((r)[17]), "r"((r)[18]), "r"((r)[19]), \
           "r"((r)[20]), "r"((r)[21]), "r"((r)[22]), "r"((r)[23]), \
           "r"((r)[24]), "r"((r)[25]), "r"((r)[26]), "r"((r)[27]), \
           "r"((r)[28]), "r"((r)[29]), "r"((r)[30]), "r"((r)[31]) \
        : "memory")

__device__ __forceinline__ void mma_tf32_ss(uint32_t d, uint64_t ad, uint64_t bd,
                                            uint32_t idesc, bool acc) {
    uint32_t en = acc ? 1u : 0u;
    asm volatile("{\n\t.reg .pred p;\n\tsetp.ne.u32 p, %5, 0;\n\t"
                 "tcgen05.mma.cta_group::1.kind::tf32 [%0], %1, %2, %3, {%4, %4, %4, %4}, p;\n\t}"
                 :: "r"(d), "l"(ad), "l"(bd), "r"(idesc), "r"(0u), "r"(en) : "memory");
}
__device__ __forceinline__ void mma_tf32_ts(uint32_t d, uint32_t a, uint64_t bd,
                                            uint32_t idesc, bool acc) {
    uint32_t en = acc ? 1u : 0u;
    asm volatile("{\n\t.reg .pred p;\n\tsetp.ne.u32 p, %5, 0;\n\t"
                 "tcgen05.mma.cta_group::1.kind::tf32 [%0], [%1], %2, %3, {%4, %4, %4, %4}, p;\n\t}"
                 :: "r"(d), "r"(a), "l"(bd), "r"(idesc), "r"(0u), "r"(en) : "memory");
}

__device__ __forceinline__ uint64_t make_desc(uint32_t addr) {
    const uint64_t base = (uint64_t(2) << 61) | (uint64_t(1) << 46)
                        | (uint64_t(64) << 32) | (uint64_t(1) << 16);
    return base | ((uint64_t)(addr >> 4) & 0x3FFF);
}
// Blocked-atom SW128 byte offset: atom = 8 rows x 32 floats.
__device__ __forceinline__ uint32_t toff(int r, int k, int R) {
    uint32_t b = ((uint32_t)((r >> 3) + (k >> 5) * R) << 10) + ((r & 7) << 7)
               + ((uint32_t)(k & 31) << 2);
    return b ^ ((b >> 3) & 0x70);
}
#define IDESC(M, N) ((1u << 4) | (2u << 7) | (2u << 10) | ((uint32_t)((N) / 8) << 17) | ((uint32_t)((M) / 16) << 24))
#endif  // HAS_TCGEN05

// ---------------------------------------------------------------------------
// GroupNorm
// ---------------------------------------------------------------------------
__global__ void __launch_bounds__(256) groupnorm_kernel(
    const float* __restrict__ x, const float* __restrict__ w,
    const float* __restrict__ bvec, float* __restrict__ out)
{
    const int grp = blockIdx.x;
    const float* xg = x + (size_t)grp * CPG * TT;
    float* og = out + (size_t)grp * CPG * TT;

    float s = 0.f, ss = 0.f;
    for (int i = threadIdx.x * 4; i < CPG * TT; i += 1024) {
        float4 v = *(const float4*)(xg + i);
        s  += v.x + v.y + v.z + v.w;
        ss += v.x * v.x + v.y * v.y + v.z * v.z + v.w * v.w;
    }
    __shared__ float rs[8], rss[8];
    #pragma unroll
    for (int o = 16; o > 0; o >>= 1) {
        s  += __shfl_xor_sync(0xffffffffu, s, o);
        ss += __shfl_xor_sync(0xffffffffu, ss, o);
    }
    const int warp = threadIdx.x >> 5, lane = threadIdx.x & 31;
    if (lane == 0) { rs[warp] = s; rss[warp] = ss; }
    __syncthreads();
    if (threadIdx.x == 0) {
        float a = 0.f, b = 0.f;
        #pragma unroll
        for (int i = 0; i < 8; i++) { a += rs[i]; b += rss[i]; }
        rs[0] = a; rss[0] = b;
    }
    __syncthreads();
    const float inv_n = 1.f / (float)(CPG * TT);
    const float mean = rs[0] * inv_n;
    const float var  = rss[0] * inv_n - mean * mean;
    const float rstd = rsqrtf(var + 1e-5f);
    const int cbase = (grp & (NG - 1)) * CPG;

    for (int i = threadIdx.x * 4; i < CPG * TT; i += 1024) {
        const int c = cbase + (i >> 10);
        const float wc = w[c] * rstd;
        const float bc = bvec[c] - mean * wc;
        float4 v = *(const float4*)(xg + i);
        float4 o;
        o.x = v.x * wc + bc; o.y = v.y * wc + bc;
        o.z = v.z * wc + bc; o.w = v.w * wc + bc;
        *(float4*)(og + i) = o;
    }
}

// ---------------------------------------------------------------------------
// tf32 tcgen05 GEMM, 256 threads, double-buffered
// ---------------------------------------------------------------------------
template <bool RESID>
__global__ void __launch_bounds__(256) gemm_tc(
    const float* __restrict__ A, const float* __restrict__ Bm,
    const float* __restrict__ bias, const float* __restrict__ resid,
    float* __restrict__ C, int M, int K)
{
#if HAS_TCGEN05
    extern __shared__ char dsm_raw[];
    const uint32_t sraw = smem_u32(dsm_raw);
    const uint32_t sal = (sraw + 1023) & ~1023u;
    char* smb = dsm_raw + (sal - sraw);
    char* Ab[2] = { smb, smb + 32768 };
    char* Bb[2] = { smb + 16384, smb + 49152 };
    const uint32_t Aaddr[2] = { sal, sal + 32768 };
    const uint32_t Baddr[2] = { sal + 16384, sal + 49152 };

    __shared__ uint32_t s_tmem;
    __shared__ __align__(8) uint64_t s_mbar[2];

    const int tid = threadIdx.x;
    const int wid = tid >> 5;
    const int lane = tid & 31;
    const int n0 = blockIdx.x * 128;
    const int m0 = blockIdx.y * 128;
    const int bz = blockIdx.z;
    Bm += (size_t)bz * K * TT;
    C  += (size_t)bz * M * TT;
    const float* rp = RESID ? resid + (size_t)bz * M * TT : nullptr;

    if (wid == 0) TC_ALLOC(smem_u32(&s_tmem), 128);
    if (tid == 0) { MBAR_INIT(smem_u32(&s_mbar[0]), 1); MBAR_INIT(smem_u32(&s_mbar[1]), 1); }
    __syncthreads();
    uint32_t tmem;
    asm volatile("ld.shared.b32 %0, [%1];" : "=r"(tmem) : "r"(smem_u32(&s_tmem)));
    const uint32_t mbar[2] = { smem_u32(&s_mbar[0]), smem_u32(&s_mbar[1]) };
    const uint32_t idesc = IDESC(128, 128);

    const int nk = K / 32;

    for (int i = 0; i < nk; i++) {
        const int bsel = i & 1;
        if (i >= 2) mbar_wait(mbar[bsel], (uint32_t)(((i >> 1) - 1) & 1));

        {   // stage A [128m x 32k]
            const int row = tid >> 1;
            const int kk = (tid & 1) * 16;
            const float* Ak = A + (size_t)(m0 + row) * K + i * 32 + kk;
            char* ab = Ab[bsel];
            #pragma unroll
            for (int u = 0; u < 4; u++) {
                const float4 v = *(const float4*)&Ak[u * 4];
                *(float4*)(ab + toff(row, kk + u * 4, 16)) = v;
            }
        }
        {   // stage B [128n x 32k] via transpose
            const int krow = tid >> 3;
            const float* Bk = Bm + (size_t)(i * 32 + krow) * TT + n0;
            char* bb = Bb[bsel];
            #pragma unroll
            for (int p = 0; p < 4; p++) {
                const int nn = (tid & 7) * 4 + p * 32;
                const float4 v = *(const float4*)&Bk[nn];
                *(float*)(bb + toff(nn + 0, krow, 16)) = v.x;
                *(float*)(bb + toff(nn + 1, krow, 16)) = v.y;
                *(float*)(bb + toff(nn + 2, krow, 16)) = v.z;
                *(float*)(bb + toff(nn + 3, krow, 16)) = v.w;
            }
        }
        __syncthreads();
        if (wid == 0 && elect_one()) {
            const uint64_t ad = make_desc(Aaddr[bsel]);
            const uint64_t bd = make_desc(Baddr[bsel]);
            #pragma unroll
            for (int j = 0; j < 4; j++)
                mma_tf32_ss(tmem, ad + j * 2, bd + j * 2, idesc, (i > 0) || (j > 0));
            TC_COMMIT(mbar[bsel]);
        }
    }
    mbar_wait(mbar[(nk - 1) & 1], (uint32_t)(((nk - 1) >> 1) & 1));
    TC_FENCE_AFTER();
    __syncthreads();

    // epilogue
    const int wg = wid >> 2;
    const int sp = wid & 3;
    const uint32_t woff = (uint32_t)sp << 21;
    const int wg_tid = tid & 127;
    float* tsm = (float*)smb;
    const int wbase = wg * 32 * 133;

    for (int it = 0; it < 2; it++) {
        const int c4 = it * 2 + wg;
        uint32_t regs[32];
        TC_LD_X32(regs, tmem + c4 * 32 + woff);
        TC_WAIT_LD();
        const int myrow = sp * 32 + lane;
        #pragma unroll
        for (int j = 0; j < 32; j++) tsm[wbase + j * 133 + myrow] = __uint_as_float(regs[j]);
        __syncthreads();
        const int n = wg_tid & 31;
        #pragma unroll
        for (int q = 0; q < 32; q++) {
            const int m = (wg_tid >> 5) + q * 4;
            float v = tsm[wbase + n * 133 + m] + bias[m0 + m];
            const size_t off = (size_t)(m0 + m) * TT + n0 + c4 * 32 + n;
            if (RESID) v += rp[off];
            C[off] = v;
        }
        __syncthreads();
    }
    if (wid == 0) { TC_RELINQ(); TC_DEALLOC(tmem, 128); }
#endif
}

// ---------------------------------------------------------------------------
// Single-pass flash attention: 256 threads, Q in TMEM, online softmax.
// TMEM: S [0,128), O [128,192), Q [192,256). mb = S commits, mb2 = PV commits.
// ---------------------------------------------------------------------------
__global__ void __launch_bounds__(256, 2) attn_tc(
    const float* __restrict__ qkv, float* __restrict__ a_out)
{
#if HAS_TCGEN05
    extern __shared__ char dsm_raw[];
    const uint32_t sraw = smem_u32(dsm_raw);
    const uint32_t sal = (sraw + 1023) & ~1023u;
    char* smb = dsm_raw + (sal - sraw);
    char* Kb = smb;                              // 128s x 64c, 32KB
    char* Vb[2] = { smb + 32768, smb + 65536 };  // 64c x 128s each, 32KB
    const uint32_t Kaddr = sal;
    const uint32_t Vaddr[2] = { sal + 32768, sal + 65536 };

    __shared__ uint32_t s_tmem;
    __shared__ __align__(8) uint64_t s_mbar[2];
    __shared__ float pmax[2][128], psum[2][128];
    __shared__ float m_s[128], l_s[128];

    const int tid = threadIdx.x;
    const int wid = tid >> 5;
    const int lane = tid & 31;
    const int sp = wid & 3;
    const int wg = wid >> 2;
    const uint32_t woff = (uint32_t)sp << 21;
    const int row = sp * 32 + lane;

    const int bh = blockIdx.y;
    const int b = bh >> 3, h = bh & 7;
    const int t0 = blockIdx.x * 128;

    const float* qp = qkv + ((size_t)(b * 3 * CC) + (size_t)h * 3 * CHH) * TT;
    const float* kp = qp + (size_t)CHH * TT;
    const float* vp = qp + (size_t)2 * CHH * TT;

    if (wid == 0) TC_ALLOC(smem_u32(&s_tmem), 256);
    if (tid == 0) { MBAR_INIT(smem_u32(&s_mbar[0]), 1); MBAR_INIT(smem_u32(&s_mbar[1]), 1); }
    if (wg == 0) { m_s[row] = -1e30f; l_s[row] = 0.f; }
    __syncthreads();
    uint32_t tmem;
    asm volatile("ld.shared.b32 %0, [%1];" : "=r"(tmem) : "r"(smem_u32(&s_tmem)));
    const uint32_t mb = smem_u32(&s_mbar[0]);
    const uint32_t mb2 = smem_u32(&s_mbar[1]);
    const uint32_t tS = tmem, tO = tmem + 128, tQ = tmem + 192;
    const uint32_t idS = IDESC(128, 128);
    const uint32_t idO = IDESC(128, 64);

    // Q -> TMEM (lane = query row, col = channel), pre-scaled by 1/8
    {
        uint32_t qreg[32];
        #pragma unroll
        for (int j = 0; j < 32; j++) {
            const int c = wg * 32 + j;
            qreg[j] = __float_as_uint(qp[(size_t)c * TT + t0 + row] * 0.125f);
        }
        TC_ST_X32(tQ + wg * 32 + woff, qreg);
        TC_WAIT_ST();
        TC_FENCE_BEFORE();
    }

    const uint64_t kdesc = make_desc(Kaddr);
    const uint64_t vdesc[2] = { make_desc(Vaddr[0]), make_desc(Vaddr[1]) };

    for (int st = 0; st < 8; st++) {
        const int s0 = st * 128;
        {   // stage K (transpose [c][t] -> [s][c]) + V (direct [c][s])
            const int c = tid >> 2;
            char* vb = Vb[st & 1];
            #pragma unroll
            for (int p = 0; p < 8; p++) {
                const int s = (tid & 3) * 4 + p * 16;
                const float4 v = *(const float4*)&kp[(size_t)c * TT + s0 + s];
                *(float*)(Kb + toff(s + 0, c, 16)) = v.x;
                *(float*)(Kb + toff(s + 1, c, 16)) = v.y;
                *(float*)(Kb + toff(s + 2, c, 16)) = v.z;
                *(float*)(Kb + toff(s + 3, c, 16)) = v.w;
                const float4 w = *(const float4*)&vp[(size_t)c * TT + s0 + s];
                *(float4*)(vb + toff(c, s, 8)) = w;
            }
        }
        __syncthreads();
        if (wid == 0 && elect_one()) {
            TC_FENCE_AFTER();                       // Q (and P/O) STTM visibility
            if (st > 0) mbar_wait(mb2, (uint32_t)((st - 1) & 1));  // PV(st-1) done
            #pragma unroll
            for (int j = 0; j < 8; j++) {
                const uint64_t off = (uint64_t)((j & 3) * 2 + (j >> 2) * 1024);
                mma_tf32_ts(tS, tQ + j * 8, kdesc + off, idS, j > 0);
            }
            TC_COMMIT(mb);
        }
        mbar_wait(mb, (uint32_t)(st & 1));          // S(st) done
        TC_FENCE_AFTER();

        // online softmax: this wg handles S cols [wg*64, wg*64+64)
        uint32_t r0[32], r1[32];
        TC_LD_X32(r0, tS + wg * 64 + woff);
        TC_LD_X32(r1, tS + wg * 64 + 32 + woff);
        TC_WAIT_LD();
        float pm = -1e30f;
        #pragma unroll
        for (int j = 0; j < 32; j++) {
            pm = fmaxf(pm, __uint_as_float(r0[j]));
            pm = fmaxf(pm, __uint_as_float(r1[j]));
        }
        pmax[wg][row] = pm;
        __syncthreads();
        const float mold = m_s[row];
        const float mnew = fmaxf(mold, fmaxf(pmax[0][row], pmax[1][row]));
        const float alpha = __expf(mold - mnew);
        float psumv = 0.f;
        #pragma unroll
        for (int j = 0; j < 32; j++) {
            float v0 = __expf(__uint_as_float(r0[j]) - mnew);
            float v1 = __expf(__uint_as_float(r1[j]) - mnew);
            psumv += v0 + v1;
            r0[j] = __float_as_uint(v0);
            r1[j] = __float_as_uint(v1);
        }
        psum[wg][row] = psumv;
        TC_ST_X32(tS + wg * 64 + woff, r0);
        TC_ST_X32(tS + wg * 64 + 32 + woff, r1);
        // O rescale: wg handles 32 of 64 O cols (PV(st-1) complete via mb2/mb waits)
        if (st > 0) {
            uint32_t o[32];
            TC_LD_X32(o, tO + wg * 32 + woff);
            TC_WAIT_LD();
            #pragma unroll
            for (int j = 0; j < 32; j++)
                o[j] = __float_as_uint(__uint_as_float(o[j]) * alpha);
            TC_ST_X32(tO + wg * 32 + woff, o);
        }
        TC_WAIT_ST();
        TC_FENCE_BEFORE();
        __syncthreads();
        if (wg == 0) {
            l_s[row] = l_s[row] * alpha + psum[0][row] + psum[1][row];
            m_s[row] = mnew;
        }
        if (wid == 0 && elect_one()) {
            TC_FENCE_AFTER();                        // P/O STTM visibility
            #pragma unroll
            for (int j = 0; j < 16; j++) {
                const uint64_t off = (uint64_t)((j & 3) * 2 + (j >> 2) * 512);
                mma_tf32_ts(tO, tS + j * 8, vdesc[st & 1] + off, idO,
                            (st > 0) || (j > 0));   // FIX R7: accumulate within st=0
            }
            TC_COMMIT(mb2);
        }
    }

    mbar_wait(mb2, 1u);   // 8th PV arrival -> parity (8-1)&1 = 1
    TC_FENCE_AFTER();
    __syncthreads();

    // epilogue: O/l, coalesced direct stores (lane = query t)
    {
        uint32_t o[32];
        TC_LD_X32(o, tO + wg * 32 + woff);
        TC_WAIT_LD();
        const float inv = 1.f / l_s[row];
        float* ao = a_out + ((size_t)(b * CC) + (size_t)h * CHH) * TT + t0;
        #pragma unroll
        for (int j = 0; j < 32; j++)
            ao[(size_t)(wg * 32 + j) * TT + row] = __uint_as_float(o[j]) * inv;
    }
    __syncthreads();
    if (wid == 0) { TC_RELINQ(); TC_DEALLOC(tmem, 256); }
#endif
}

// ---------------------------------------------------------------------------
extern "C" void kernel_launch(void* const* d_in, const int* in_sizes, int n_in,
                              void* d_out, int out_size)
{
    const float* x      = (const float*)d_in[0];
    const float* norm_w = (const float*)d_in[1];
    const float* norm_b = (const float*)d_in[2];
    const float* qkv_w  = (const float*)d_in[3];
    const float* qkv_b  = (const float*)d_in[4];
    const float* proj_w = (const float*)d_in[5];
    const float* proj_b = (const float*)d_in[6];
    float* out = (float*)d_out;

    float *h_buf, *qkv_buf, *a_buf;
    cudaGetSymbolAddress((void**)&h_buf, g_h);
    cudaGetSymbolAddress((void**)&qkv_buf, g_qkv);
    cudaGetSymbolAddress((void**)&a_buf, g_a);

    const int GEMM_SMEM = 66560;
    const int ATTN_SMEM = 99328;
    cudaFuncSetAttribute(gemm_tc<false>, cudaFuncAttributeMaxDynamicSharedMemorySize, GEMM_SMEM);
    cudaFuncSetAttribute(gemm_tc<true>,  cudaFuncAttributeMaxDynamicSharedMemorySize, GEMM_SMEM);
    cudaFuncSetAttribute(attn_tc, cudaFuncAttributeMaxDynamicSharedMemorySize, ATTN_SMEM);

    groupnorm_kernel<<<BB * NG, 256>>>(x, norm_w, norm_b, h_buf);
    gemm_tc<false><<<dim3(TT / 128, 3 * CC / 128, BB), 256, GEMM_SMEM>>>(
        qkv_w, h_buf, qkv_b, nullptr, qkv_buf, 3 * CC, CC);
    attn_tc<<<dim3(TT / 128, BB * NHH), 256, ATTN_SMEM>>>(qkv_buf, a_buf);
    gemm_tc<true><<<dim3(TT / 128, CC / 128, BB), 256, GEMM_SMEM>>>(
        proj_w, a_buf, proj_b, x, out, CC, CC);
}